// round 17
// baseline (speedup 1.0000x reference)
#include <cuda_runtime.h>
#include <cuda_bf16.h>
#include <cstdint>

// DGCRM: after dead-code elimination, output = GRU cell over 16384 rows:
//   c = [h(64), x(2)]  (permuted combined vector, 66 wide)
//   z = sigmoid(c @ Wz + bz); r = sigmoid(c @ Wr + br)
//   cand = [r*h, x];  hc = tanh(cand @ Wc + bc)
//   out = z*h + (1-z)*hc
//
// R15 -> R16: LDG and LDS share L1TEX (that port saturated 42-62% in every
// prior design). Weights (50.7KB) now live in __constant__ memory -> separate
// const-cache port, warp-uniform broadcast addresses (lane = row, warp = 16
// cols). L1TEX carries only 1 LDS.64 per j per warp. fold_kernel -> device
// global -> graph-captured D2D memcpy into the constant symbols.

#define CIN 66
#define HIDD 64
#define RPB 64
#define TPB 128
#define ATS 66   // transposed tile stride (even: keeps float2 loads 8B-aligned)

__device__ __align__(16) float g_Wf[3 * CIN * HIDD];
__device__ __align__(16) float g_Bf[3 * HIDD];

__constant__ __align__(16) float c_W[3 * CIN * HIDD];  // 50688 bytes
__constant__ __align__(16) float c_B[3 * HIDD];

__device__ __forceinline__ unsigned long long pk2(float a, float b) {
    unsigned long long r;
    asm("mov.b64 %0, {%1, %2};" : "=l"(r) : "f"(a), "f"(b));
    return r;
}
__device__ __forceinline__ void upk2(unsigned long long v, float& a, float& b) {
    asm("mov.b64 {%0, %1}, %2;" : "=f"(a), "=f"(b) : "l"(v));
}
__device__ __forceinline__ void fma2(unsigned long long& d, unsigned long long a, unsigned long long b) {
    asm("fma.rn.f32x2 %0, %1, %2, %0;" : "+l"(d) : "l"(a), "l"(b));
}
__device__ __forceinline__ float fsig(float v) { return 1.f / (1.f + __expf(-v)); }
__device__ __forceinline__ float ftanh(float v) { return 1.f - 2.f / (__expf(2.f * v) + 1.f); }

// Fold rnn_W[6,198,64] -> 3 effective [66,64] matrices + biases, with row
// permutation (combined [x,h] order -> stored [h,x] order).
__global__ void fold_kernel(const float* __restrict__ W, const float* __restrict__ bvec) {
    int idx = blockIdx.x * blockDim.x + threadIdx.x;
    if (idx < 3 * CIN * HIDD) {
        int m = idx / (CIN * HIDD);
        int rem = idx - m * (CIN * HIDD);
        int j = rem / HIDD;
        int col = rem - j * HIDD;
        int k = (j < HIDD) ? (j + 2) : (j - HIDD);
        float s = 0.f;
#pragma unroll
        for (int t = 0; t < 2; ++t) {
            const float* base = W + (size_t)(2 * m + t) * 198 * HIDD + col;
            s += base[(size_t)k * HIDD]
               + 0.05f * (base[(size_t)(66 + k) * HIDD] + base[(size_t)(132 + k) * HIDD]);
        }
        g_Wf[idx] = s;
    }
    if (idx < 3 * HIDD) {
        int m = idx / HIDD, j = idx - m * HIDD;
        g_Bf[idx] = bvec[(2 * m) * HIDD + j] + bvec[(2 * m + 1) * HIDD + j];
    }
}

// Block: 64 rows x 64 cols. 4 warps; warp w -> cols [16w, 16w+16).
// Lane -> rows {2*lane, 2*lane+1}. Weight addresses are warp-uniform ->
// const-cache broadcast, zero L1TEX traffic for weights.
__global__ void __launch_bounds__(TPB, 4) dgcrm_main(
    const float* __restrict__ x, const float* __restrict__ h0, float* __restrict__ out)
{
    __shared__ float At[CIN * ATS];   // [h,x] transposed: At[c][row]
    __shared__ float Ac[CIN * ATS];   // candidate [r*h, x] transposed

    const int tid  = threadIdx.x;
    const int lane = tid & 31;
    const int c0   = (tid >> 5) * 16;
    const int g0   = blockIdx.x * RPB;

    // Stage A transposed.
#pragma unroll
    for (int it = 0; it < 8; ++it) {
        int i = tid + TPB * it;           // 0..1023 = 64 rows x 16 quads
        int r = i >> 4, q = i & 15;
        float4 v = *(const float4*)(h0 + (size_t)(g0 + r) * HIDD + q * 4);
        At[(q * 4 + 0) * ATS + r] = v.x;
        At[(q * 4 + 1) * ATS + r] = v.y;
        At[(q * 4 + 2) * ATS + r] = v.z;
        At[(q * 4 + 3) * ATS + r] = v.w;
    }
    if (tid < RPB) {
        float2 v = *(const float2*)(x + (size_t)(g0 + tid) * 2);
        At[64 * ATS + tid] = v.x;  At[65 * ATS + tid] = v.y;
        Ac[64 * ATS + tid] = v.x;  Ac[65 * ATS + tid] = v.y;
    }
    __syncthreads();

    unsigned long long zacc[16], racc[16];   // [row(2)][col-pair(8)]
#pragma unroll
    for (int i = 0; i < 16; ++i) { zacc[i] = 0ull; racc[i] = 0ull; }

    // ---- phase 1: z,r GEMMs. Weights via warp-uniform LDC.128. ----
#pragma unroll 3
    for (int j = 0; j < CIN; ++j) {
        const float2 a = *(const float2*)(At + j * ATS + 2 * lane);
        const unsigned long long a0 = pk2(a.x, a.x);
        const unsigned long long a1 = pk2(a.y, a.y);
        const ulonglong2* wz = (const ulonglong2*)(c_W + j * HIDD + c0);
        const ulonglong2* wr = (const ulonglong2*)(c_W + CIN * HIDD + j * HIDD + c0);
        ulonglong2 u;
        u = wz[0]; fma2(zacc[0], a0, u.x); fma2(zacc[1], a0, u.y);
                   fma2(zacc[8], a1, u.x); fma2(zacc[9], a1, u.y);
        u = wz[1]; fma2(zacc[2], a0, u.x); fma2(zacc[3], a0, u.y);
                   fma2(zacc[10], a1, u.x); fma2(zacc[11], a1, u.y);
        u = wz[2]; fma2(zacc[4], a0, u.x); fma2(zacc[5], a0, u.y);
                   fma2(zacc[12], a1, u.x); fma2(zacc[13], a1, u.y);
        u = wz[3]; fma2(zacc[6], a0, u.x); fma2(zacc[7], a0, u.y);
                   fma2(zacc[14], a1, u.x); fma2(zacc[15], a1, u.y);
        u = wr[0]; fma2(racc[0], a0, u.x); fma2(racc[1], a0, u.y);
                   fma2(racc[8], a1, u.x); fma2(racc[9], a1, u.y);
        u = wr[1]; fma2(racc[2], a0, u.x); fma2(racc[3], a0, u.y);
                   fma2(racc[10], a1, u.x); fma2(racc[11], a1, u.y);
        u = wr[2]; fma2(racc[4], a0, u.x); fma2(racc[5], a0, u.y);
                   fma2(racc[12], a1, u.x); fma2(racc[13], a1, u.y);
        u = wr[3]; fma2(racc[6], a0, u.x); fma2(racc[7], a0, u.y);
                   fma2(racc[14], a1, u.x); fma2(racc[15], a1, u.y);
    }

    // ---- candidate: Ac[c][row] = sigmoid(r + br) * h (own lanes only;
    //      At untouched, so no sync needed before this) ----
#pragma unroll
    for (int i = 0; i < 8; ++i) {
        const int c = c0 + 2 * i;
        const float b0 = c_B[HIDD + c], b1 = c_B[HIDD + c + 1];
        float r00, r01, r10, r11;
        upk2(racc[i], r00, r01);        // row 2*lane,   cols c, c+1
        upk2(racc[8 + i], r10, r11);    // row 2*lane+1
        Ac[c * ATS + 2 * lane]           = fsig(r00 + b0) * At[c * ATS + 2 * lane];
        Ac[(c + 1) * ATS + 2 * lane]     = fsig(r01 + b1) * At[(c + 1) * ATS + 2 * lane];
        Ac[c * ATS + 2 * lane + 1]       = fsig(r10 + b0) * At[c * ATS + 2 * lane + 1];
        Ac[(c + 1) * ATS + 2 * lane + 1] = fsig(r11 + b1) * At[(c + 1) * ATS + 2 * lane + 1];
    }
    __syncthreads();   // phase 2 reads every warp's candidate columns

    // ---- phase 2: hc GEMM over candidate ----
    unsigned long long cacc[16];
#pragma unroll
    for (int i = 0; i < 16; ++i) cacc[i] = 0ull;
#pragma unroll 3
    for (int j = 0; j < CIN; ++j) {
        const float2 a = *(const float2*)(Ac + j * ATS + 2 * lane);
        const unsigned long long a0 = pk2(a.x, a.x);
        const unsigned long long a1 = pk2(a.y, a.y);
        const ulonglong2* wc = (const ulonglong2*)(c_W + 2 * CIN * HIDD + j * HIDD + c0);
        ulonglong2 u;
        u = wc[0]; fma2(cacc[0], a0, u.x); fma2(cacc[1], a0, u.y);
                   fma2(cacc[8], a1, u.x); fma2(cacc[9], a1, u.y);
        u = wc[1]; fma2(cacc[2], a0, u.x); fma2(cacc[3], a0, u.y);
                   fma2(cacc[10], a1, u.x); fma2(cacc[11], a1, u.y);
        u = wc[2]; fma2(cacc[4], a0, u.x); fma2(cacc[5], a0, u.y);
                   fma2(cacc[12], a1, u.x); fma2(cacc[13], a1, u.y);
        u = wc[3]; fma2(cacc[6], a0, u.x); fma2(cacc[7], a0, u.y);
                   fma2(cacc[14], a1, u.x); fma2(cacc[15], a1, u.y);
    }

    // ---- epilogue: out = z*h + (1-z)*hc ----
#pragma unroll
    for (int rr = 0; rr < 2; ++rr) {
        const int row = 2 * lane + rr;
        float ov[16];
#pragma unroll
        for (int i = 0; i < 8; ++i) {
            const int c = c0 + 2 * i;
            float za, zb, ca, cb;
            upk2(zacc[8 * rr + i], za, zb);
            upk2(cacc[8 * rr + i], ca, cb);
            za = fsig(za + c_B[c]);
            zb = fsig(zb + c_B[c + 1]);
            ca = ftanh(ca + c_B[2 * HIDD + c]);
            cb = ftanh(cb + c_B[2 * HIDD + c + 1]);
            const float ha = At[c * ATS + row];
            const float hb = At[(c + 1) * ATS + row];
            ov[2 * i]     = za * ha + (1.f - za) * ca;
            ov[2 * i + 1] = zb * hb + (1.f - zb) * cb;
        }
        float* orow = out + (size_t)(g0 + row) * HIDD + c0;
#pragma unroll
        for (int q = 0; q < 4; ++q) {
            float4 o;
            o.x = ov[4 * q]; o.y = ov[4 * q + 1]; o.z = ov[4 * q + 2]; o.w = ov[4 * q + 3];
            *(float4*)(orow + 4 * q) = o;
        }
    }
}

extern "C" void kernel_launch(void* const* d_in, const int* in_sizes, int n_in,
                              void* d_out, int out_size) {
    (void)in_sizes; (void)n_in; (void)out_size;
    const float* x    = (const float*)d_in[0];    // [16,1024,2]
    const float* h0   = (const float*)d_in[1];    // [16,1024,64]
    const float* rnnW = (const float*)d_in[12];   // [6,198,64]
    const float* rnnb = (const float*)d_in[13];   // [6,64]
    float* out = (float*)d_out;                   // [16,1024,64]

    void *pW = nullptr, *pB = nullptr, *pgW = nullptr, *pgB = nullptr;
    cudaGetSymbolAddress(&pW, c_W);
    cudaGetSymbolAddress(&pB, c_B);
    cudaGetSymbolAddress(&pgW, g_Wf);
    cudaGetSymbolAddress(&pgB, g_Bf);

    fold_kernel<<<(3 * CIN * HIDD + 255) / 256, 256>>>(rnnW, rnnb);
    cudaMemcpyAsync(pW, pgW, 3 * CIN * HIDD * sizeof(float), cudaMemcpyDeviceToDevice);
    cudaMemcpyAsync(pB, pgB, 3 * HIDD * sizeof(float), cudaMemcpyDeviceToDevice);
    dgcrm_main<<<16384 / RPB, TPB>>>(x, h0, out);
}